// round 15
// baseline (speedup 1.0000x reference)
#include <cuda_runtime.h>
#include <cuda_bf16.h>
#include <cstdint>

// InnerProduct_65429531787441 — HMMA bf16-split v4: warp-specialized pipeline.
//   X [B,50,64] f32, Theta [128,50] f32
//   proj = einsum("df,bfe->bde"); out[b,d] = sum_e proj^2 -> [B,128] f32
//
// vs R14 (123.6us, tensor=51.8%): the ~60us tensor-idle tail (convert+
// epilogue in every warp) is removed from the MMA warps. 8 MMA warps only
// run HMMA+rank2+epilogue; 2 producer (CVT) warps do all X loading,
// bf16 hi/lo splitting (fast cvt.rn.bf16x2 + shift/mask residual), and
// fragment STS, handing off stages through full/empty mbarriers.

#define F_DIM 50
#define E_DIM 64
#define D_DIM 128
#define NTHREADS 320          // 256 MMA + 64 CVT
#define GRID 296
#define KS_N 3                // dense k16 chunks (k < 48)

struct Smem {
    uint32_t Al[4][2][KS_N][32][4];     // Theta-lo frags            12 KB
    uint32_t BH[2][KS_N * 8 * 32 * 2];  // X-hi frags [stage]        12 KB
    uint32_t BL[2][KS_N * 8 * 32 * 2];  // X-lo frags                12 KB
    float    Xt[2][128];                // rows 48,49 (fp32 tail)     1 KB
    float    red[2][2][128];            // [stage][nh][d]             2 KB
    unsigned long long full[2];         // CVT -> MMA (count 2)
    unsigned long long empty[2];        // MMA -> CVT (count 8)
};

__device__ __forceinline__ void mma_bf16(float* c, const uint32_t* a,
                                         uint32_t b0, uint32_t b1) {
    asm("mma.sync.aligned.m16n8k16.row.col.f32.bf16.bf16.f32 "
        "{%0,%1,%2,%3}, {%4,%5,%6,%7}, {%8,%9}, {%0,%1,%2,%3};"
        : "+f"(c[0]), "+f"(c[1]), "+f"(c[2]), "+f"(c[3])
        : "r"(a[0]), "r"(a[1]), "r"(a[2]), "r"(a[3]), "r"(b0), "r"(b1));
}

__device__ __forceinline__ uint32_t split_pack(float v0, float v1,
                                               uint32_t& lo_out) {
    __nv_bfloat16 h0 = __float2bfloat16(v0);
    __nv_bfloat16 h1 = __float2bfloat16(v1);
    __nv_bfloat16 l0 = __float2bfloat16(v0 - __bfloat162float(h0));
    __nv_bfloat16 l1 = __float2bfloat16(v1 - __bfloat162float(h1));
    __nv_bfloat162 hp(h0, h1), lp(l0, l1);
    lo_out = *reinterpret_cast<uint32_t*>(&lp);
    return *reinterpret_cast<uint32_t*>(&hp);
}

// Fast split: one bf16x2 cvt for hi, residual via shift/mask, one cvt for lo.
__device__ __forceinline__ uint32_t split_pack_fast(float v0, float v1,
                                                    uint32_t& lo_out) {
    uint32_t hi;
    asm("cvt.rn.bf16x2.f32 %0, %1, %2;" : "=r"(hi) : "f"(v1), "f"(v0));
    float hf0 = __uint_as_float(hi << 16);            // bf16(v0) as f32
    float hf1 = __uint_as_float(hi & 0xffff0000u);    // bf16(v1) as f32
    float l0 = v0 - hf0, l1 = v1 - hf1;
    asm("cvt.rn.bf16x2.f32 %0, %1, %2;" : "=r"(lo_out) : "f"(l1), "f"(l0));
    return hi;
}

__device__ __forceinline__ void mbar_wait(uint32_t mbar, uint32_t par) {
    asm volatile(
        "{\n\t.reg .pred P1;\n\t"
        "WL_%=:\n\t"
        "mbarrier.try_wait.parity.acquire.cta.shared::cta.b64 P1, [%0], %1, 0x989680;\n\t"
        "@P1 bra.uni WD_%=;\n\t"
        "bra.uni WL_%=;\n\t"
        "WD_%=:\n\t}"
        :: "r"(mbar), "r"(par) : "memory");
}

__device__ __forceinline__ uint32_t smem_u32(const void* p) {
    uint32_t a;
    asm("{ .reg .u64 t; cvta.to.shared.u64 t, %1; cvt.u32.u64 %0, t; }"
        : "=r"(a) : "l"(p));
    return a;
}

__global__ void __launch_bounds__(NTHREADS, 2)
ip_hmma4(const float* __restrict__ X, const float* __restrict__ Theta,
         float* __restrict__ out, int Btot) {
    extern __shared__ char smem_raw[];
    Smem& S = *reinterpret_cast<Smem*>(smem_raw);

    const int t = threadIdx.x;
    const int l = t & 31;
    const int stride = (int)gridDim.x;
    const int b0 = (int)blockIdx.x;

    const uint32_t mb_full0  = smem_u32(&S.full[0]);
    const uint32_t mb_full1  = smem_u32(&S.full[1]);
    const uint32_t mb_empty0 = smem_u32(&S.empty[0]);
    const uint32_t mb_empty1 = smem_u32(&S.empty[1]);

    if (t == 0) {
        asm volatile("mbarrier.init.shared.b64 [%0], 2;" :: "r"(mb_full0));
        asm volatile("mbarrier.init.shared.b64 [%0], 2;" :: "r"(mb_full1));
        asm volatile("mbarrier.init.shared.b64 [%0], 8;" :: "r"(mb_empty0));
        asm volatile("mbarrier.init.shared.b64 [%0], 8;" :: "r"(mb_empty1));
    }

    // ---- MMA persona state (computed by t<256 only) ----
    uint32_t Ah[2][KS_N][4];
    float tT[2][2][2];

    if (t < 256) {
        const int w    = t >> 5;
        const int mblk = w & 3;
        const int nh   = w >> 2;
        const int lg   = l >> 2;
        const int la   = l & 3;
        #pragma unroll
        for (int mt = 0; mt < 2; mt++)
            #pragma unroll
            for (int ks = 0; ks < KS_N; ks++)
                #pragma unroll
                for (int rg = 0; rg < 4; rg++) {
                    int row = mblk * 32 + mt * 16 + lg + ((rg & 1) ? 8 : 0);
                    int k   = ks * 16 + la * 2 + ((rg & 2) ? 8 : 0);
                    uint32_t lo;
                    Ah[mt][ks][rg] = split_pack(Theta[row * F_DIM + k],
                                                Theta[row * F_DIM + k + 1], lo);
                    if (nh == 0) S.Al[mblk][mt][ks][l][rg] = lo;
                }
        #pragma unroll
        for (int mt = 0; mt < 2; mt++)
            #pragma unroll
            for (int h = 0; h < 2; h++) {
                int row = mblk * 32 + mt * 16 + lg + h * 8;
                tT[mt][h][0] = Theta[row * F_DIM + 48];
                tT[mt][h][1] = Theta[row * F_DIM + 49];
            }
    }
    __syncthreads();   // mbarriers + Al visible to everyone

    if (t >= 256) {
        // ================= CVT (producer) persona: 2 warps =================
        const int ct = t - 256;            // 0..63
        int stage = 0, phE = 1;            // producer starts at parity 1
        for (int b = b0; b < Btot; b += stride) {
            mbar_wait(stage ? mb_empty1 : mb_empty0, (uint32_t)phE);
            const float* Xb = X + (size_t)b * (F_DIM * E_DIM);
            // 1536 (fp-pair, e) points: j-th step covers combos 2j, 2j+1.
            #pragma unroll 6
            for (int j = 0; j < 24; j++) {
                int combo = 2 * j + (ct >> 5);
                int ks = combo >> 4, r = (combo >> 3) & 1, nt = combo & 7;
                int fp = ks * 8 + r * 4 + (l & 3);
                int e  = nt * 8 + (l >> 2);
                float v0 = __ldg(Xb + 2 * fp * E_DIM + e);
                float v1 = __ldg(Xb + (2 * fp + 1) * E_DIM + e);
                uint32_t lo;
                uint32_t hi = split_pack_fast(v0, v1, lo);
                int idx = ((ks * 8 + nt) * 32 + l) * 2 + r;
                S.BH[stage][idx] = hi;
                S.BL[stage][idx] = lo;
            }
            {   // fp32 tail rows 48,49: 2 elems per thread
                int xi2 = ct * 2;
                const float2 xv = *reinterpret_cast<const float2*>(
                    Xb + (48 + (xi2 >> 6)) * E_DIM + (xi2 & 63));
                *reinterpret_cast<float2*>(&S.Xt[stage][xi2]) = xv;
            }
            __syncwarp();
            if (l == 0) {
                asm volatile("mbarrier.arrive.shared.b64 _, [%0];"
                             :: "r"(stage ? mb_full1 : mb_full0) : "memory");
            }
            stage ^= 1;
            if (!stage) phE ^= 1;
        }
    } else {
        // ================= MMA (consumer) persona: 8 warps =================
        const int w    = t >> 5;
        const int mblk = w & 3;
        const int nh   = w >> 2;
        const int lg   = l >> 2;
        const int la   = l & 3;

        int stage = 0, phF = 0;
        for (int b = b0; b < Btot; b += stride) {
            mbar_wait(stage ? mb_full1 : mb_full0, (uint32_t)phF);

            float C[2][4][4];
            #pragma unroll
            for (int mt = 0; mt < 2; mt++)
                #pragma unroll
                for (int ntl = 0; ntl < 4; ntl++)
                    #pragma unroll
                    for (int rg = 0; rg < 4; rg++) C[mt][ntl][rg] = 0.f;

            // ---- mainloop: 72 HMMA ----
            #pragma unroll
            for (int ks = 0; ks < KS_N; ks++) {
                uint32_t AL0[4], AL1[4];
                {
                    uint4 a0 = *reinterpret_cast<const uint4*>(&S.Al[mblk][0][ks][l][0]);
                    uint4 a1 = *reinterpret_cast<const uint4*>(&S.Al[mblk][1][ks][l][0]);
                    AL0[0] = a0.x; AL0[1] = a0.y; AL0[2] = a0.z; AL0[3] = a0.w;
                    AL1[0] = a1.x; AL1[1] = a1.y; AL1[2] = a1.z; AL1[3] = a1.w;
                }
                #pragma unroll
                for (int ntl = 0; ntl < 4; ntl++) {
                    int nt = nh * 4 + ntl;
                    int base = ((ks * 8 + nt) * 32 + l) * 2;
                    uint2 bh = *reinterpret_cast<const uint2*>(&S.BH[stage][base]);
                    uint2 bl = *reinterpret_cast<const uint2*>(&S.BL[stage][base]);
                    mma_bf16(C[0][ntl], Ah[0][ks], bh.x, bh.y);
                    mma_bf16(C[1][ntl], Ah[1][ks], bh.x, bh.y);
                    mma_bf16(C[0][ntl], Ah[0][ks], bl.x, bl.y);
                    mma_bf16(C[1][ntl], Ah[1][ks], bl.x, bl.y);
                    mma_bf16(C[0][ntl], AL0,       bh.x, bh.y);
                    mma_bf16(C[1][ntl], AL1,       bh.x, bh.y);
                }
            }

            // ---- exact fp32 rank-2 tail (k = 48,49) ----
            #pragma unroll
            for (int ntl = 0; ntl < 4; ntl++) {
                int e0 = nh * 32 + ntl * 8 + 2 * la;
                float2 x48 = *reinterpret_cast<const float2*>(&S.Xt[stage][e0]);
                float2 x49 = *reinterpret_cast<const float2*>(&S.Xt[stage][64 + e0]);
                #pragma unroll
                for (int mt = 0; mt < 2; mt++) {
                    C[mt][ntl][0] = fmaf(tT[mt][0][0], x48.x,
                                    fmaf(tT[mt][0][1], x49.x, C[mt][ntl][0]));
                    C[mt][ntl][1] = fmaf(tT[mt][0][0], x48.y,
                                    fmaf(tT[mt][0][1], x49.y, C[mt][ntl][1]));
                    C[mt][ntl][2] = fmaf(tT[mt][1][0], x48.x,
                                    fmaf(tT[mt][1][1], x49.x, C[mt][ntl][2]));
                    C[mt][ntl][3] = fmaf(tT[mt][1][0], x48.y,
                                    fmaf(tT[mt][1][1], x49.y, C[mt][ntl][3]));
                }
            }

            // Release the stage to the producer BEFORE the epilogue.
            __syncwarp();
            if (l == 0) {
                asm volatile("mbarrier.arrive.shared.b64 _, [%0];"
                             :: "r"(stage ? mb_empty1 : mb_empty0) : "memory");
            }

            // ---- epilogue: sum_e proj^2 ----
            float s[2][2] = {{0.f, 0.f}, {0.f, 0.f}};
            #pragma unroll
            for (int mt = 0; mt < 2; mt++)
                #pragma unroll
                for (int ntl = 0; ntl < 4; ntl++) {
                    s[mt][0] = fmaf(C[mt][ntl][0], C[mt][ntl][0],
                               fmaf(C[mt][ntl][1], C[mt][ntl][1], s[mt][0]));
                    s[mt][1] = fmaf(C[mt][ntl][2], C[mt][ntl][2],
                               fmaf(C[mt][ntl][3], C[mt][ntl][3], s[mt][1]));
                }
            #pragma unroll
            for (int mt = 0; mt < 2; mt++)
                #pragma unroll
                for (int h = 0; h < 2; h++) {
                    float v = s[mt][h];
                    v += __shfl_xor_sync(0xffffffffu, v, 1);
                    v += __shfl_xor_sync(0xffffffffu, v, 2);
                    s[mt][h] = v;
                }
            if (la == 0) {
                #pragma unroll
                for (int mt = 0; mt < 2; mt++) {
                    S.red[stage][nh][mblk * 32 + mt * 16 + lg]     = s[mt][0];
                    S.red[stage][nh][mblk * 32 + mt * 16 + lg + 8] = s[mt][1];
                }
            }
            asm volatile("bar.sync 1, 256;" ::: "memory");   // MMA warps only
            if (t < D_DIM)
                out[(size_t)b * D_DIM + t] =
                    S.red[stage][0][t] + S.red[stage][1][t];

            stage ^= 1;
            if (!stage) phF ^= 1;
        }
    }
}

extern "C" void kernel_launch(void* const* d_in, const int* in_sizes, int n_in,
                              void* d_out, int out_size) {
    int xi = 0, ti = 1;
    if (n_in >= 2 && in_sizes[0] < in_sizes[1]) { xi = 1; ti = 0; }

    const float* X     = (const float*)d_in[xi];
    const float* Theta = (const float*)d_in[ti];
    float*       out   = (float*)d_out;
    int Btot = in_sizes[xi] / (F_DIM * E_DIM);

    cudaFuncSetAttribute(ip_hmma4, cudaFuncAttributeMaxDynamicSharedMemorySize,
                         (int)sizeof(Smem));
    ip_hmma4<<<GRID, NTHREADS, sizeof(Smem)>>>(X, Theta, out, Btot);
}

// round 17
// speedup vs baseline: 1.5732x; 1.5732x over previous
#include <cuda_runtime.h>
#include <cuda_bf16.h>
#include <cstdint>

// InnerProduct_65429531787441 — HMMA bf16-split v5.
//   X [B,50,64] f32, Theta [128,50] f32
//   proj = einsum("df,bfe->bde"); out[b,d] = sum_e proj^2 -> [B,128] f32
//
// Base = R14 (123.6us, tensor=51.8%). R15's warp specialization regressed
// (2 producer warps latency-bound) and is reverted.
// Changes vs R14:
//  (1) mainloop reordered: per ks, load B frags for all 4 ntl first, then
//      sweep passes (AhBh / AhBl / AlBh) across ntl x mt -> accumulator
//      reuse distance 8 HMMAs (> HMMA RAW latency) instead of 2.
//  (2) convert() of the next batch issued before the rank-2/epilogue,
//      shortening the post-HMMA tail to the barrier.

#define F_DIM 50
#define E_DIM 64
#define D_DIM 128
#define NTHREADS 256
#define GRID 296
#define KS_N 3                       // dense k16 chunks (k < 48)

struct Smem {
    uint32_t Al[4][2][KS_N][32][4];     // [mblk][mt][ks][lane][rg]  12 KB
    uint32_t BH[2][KS_N * 8 * 32 * 2];  // [buf][((ks*8+nt)*32+l)*2+r] 12 KB
    uint32_t BL[2][KS_N * 8 * 32 * 2];  //                            12 KB
    float    Xt[2][128];                // [buf][e | 64+e] rows 48,49   1 KB
    float    red[2][2][128];            // [parity][nh][d]              2 KB
};

__device__ __forceinline__ void mma_bf16(float* c, const uint32_t* a,
                                         uint32_t b0, uint32_t b1) {
    asm("mma.sync.aligned.m16n8k16.row.col.f32.bf16.bf16.f32 "
        "{%0,%1,%2,%3}, {%4,%5,%6,%7}, {%8,%9}, {%0,%1,%2,%3};"
        : "+f"(c[0]), "+f"(c[1]), "+f"(c[2]), "+f"(c[3])
        : "r"(a[0]), "r"(a[1]), "r"(a[2]), "r"(a[3]), "r"(b0), "r"(b1));
}

__device__ __forceinline__ uint32_t split_pack(float v0, float v1,
                                               uint32_t& lo_out) {
    __nv_bfloat16 h0 = __float2bfloat16(v0);
    __nv_bfloat16 h1 = __float2bfloat16(v1);
    __nv_bfloat16 l0 = __float2bfloat16(v0 - __bfloat162float(h0));
    __nv_bfloat16 l1 = __float2bfloat16(v1 - __bfloat162float(h1));
    __nv_bfloat162 hp(h0, h1), lp(l0, l1);
    lo_out = *reinterpret_cast<uint32_t*>(&lp);
    return *reinterpret_cast<uint32_t*>(&hp);
}

// Fast split: bf16x2 cvt for hi, residual via bit ops, one cvt for lo.
__device__ __forceinline__ uint32_t split_pack_fast(float v0, float v1,
                                                    uint32_t& lo_out) {
    uint32_t hi;
    asm("cvt.rn.bf16x2.f32 %0, %1, %2;" : "=r"(hi) : "f"(v1), "f"(v0));
    float hf0 = __uint_as_float(hi << 16);
    float hf1 = __uint_as_float(hi & 0xffff0000u);
    float l0 = v0 - hf0, l1 = v1 - hf1;
    asm("cvt.rn.bf16x2.f32 %0, %1, %2;" : "=r"(lo_out) : "f"(l1), "f"(l0));
    return hi;
}

__global__ void __launch_bounds__(NTHREADS, 2)
ip_hmma5(const float* __restrict__ X, const float* __restrict__ Theta,
         float* __restrict__ out, int Btot) {
    extern __shared__ char smem_raw[];
    Smem& S = *reinterpret_cast<Smem*>(smem_raw);

    const int t    = threadIdx.x;
    const int w    = t >> 5;
    const int l    = t & 31;
    const int mblk = w & 3;    // M32 row block
    const int nh   = w >> 2;   // N32 col half
    const int lg   = l >> 2;   // quad group (0..7)
    const int la   = l & 3;    // lane in quad

    // ---- Theta fragments: hi in registers, lo to shared (once) ----
    uint32_t Ah[2][KS_N][4];
    #pragma unroll
    for (int mt = 0; mt < 2; mt++)
        #pragma unroll
        for (int ks = 0; ks < KS_N; ks++)
            #pragma unroll
            for (int rg = 0; rg < 4; rg++) {
                int row = mblk * 32 + mt * 16 + lg + ((rg & 1) ? 8 : 0);
                int k   = ks * 16 + la * 2 + ((rg & 2) ? 8 : 0);   // <= 46
                uint32_t lo;
                Ah[mt][ks][rg] = split_pack(Theta[row * F_DIM + k],
                                            Theta[row * F_DIM + k + 1], lo);
                if (nh == 0) S.Al[mblk][mt][ks][l][rg] = lo;
            }

    // Exact fp32 tail Theta (k = 48,49) for this warp's 4 row slots.
    float tT[2][2][2];
    #pragma unroll
    for (int mt = 0; mt < 2; mt++)
        #pragma unroll
        for (int h = 0; h < 2; h++) {
            int row = mblk * 32 + mt * 16 + lg + h * 8;
            tT[mt][h][0] = Theta[row * F_DIM + 48];
            tT[mt][h][1] = Theta[row * F_DIM + 49];
        }

    const int stride = (int)gridDim.x;
    const int b0 = (int)blockIdx.x;

    float xr[6][2];
    float xt = 0.f;

    auto prefetch = [&](int b) {
        const float* Xb = X + (size_t)b * (F_DIM * E_DIM);
        #pragma unroll
        for (int j = 0; j < 6; j++) {
            int combo = w * 6 + j;                      // 0..47
            int ks = combo >> 4, r = (combo >> 3) & 1, nt = combo & 7;
            int fp = ks * 8 + r * 4 + la;               // k = 2*fp < 48
            int e  = nt * 8 + lg;
            xr[j][0] = __ldg(Xb + 2 * fp * E_DIM + e);
            xr[j][1] = __ldg(Xb + (2 * fp + 1) * E_DIM + e);
        }
        if (t < 128) xt = __ldg(Xb + (48 + (t >> 6)) * E_DIM + (t & 63));
    };
    auto convert = [&](int buf) {
        #pragma unroll
        for (int j = 0; j < 6; j++) {
            int combo = w * 6 + j;
            int ks = combo >> 4, r = (combo >> 3) & 1, nt = combo & 7;
            int idx = ((ks * 8 + nt) * 32 + l) * 2 + r;
            uint32_t lo;
            uint32_t hi = split_pack_fast(xr[j][0], xr[j][1], lo);
            S.BH[buf][idx] = hi;
            S.BL[buf][idx] = lo;
        }
        if (t < 128) S.Xt[buf][t] = xt;
    };

    if (b0 < Btot) { prefetch(b0); convert(0); }
    __syncthreads();

    int i = 0;
    for (int b = b0; b < Btot; b += stride, i++) {
        const int cur = i & 1;
        const int bn  = b + stride;
        if (bn < Btot) prefetch(bn);          // DRAM under HMMA

        float C[2][4][4];
        #pragma unroll
        for (int mt = 0; mt < 2; mt++)
            #pragma unroll
            for (int ntl = 0; ntl < 4; ntl++)
                #pragma unroll
                for (int rg = 0; rg < 4; rg++) C[mt][ntl][rg] = 0.f;

        // ---- mainloop: 72 HMMA, 8-deep accumulator interleave ----
        #pragma unroll
        for (int ks = 0; ks < KS_N; ks++) {
            // Load B fragments for all 4 ntl up front.
            uint2 Bh[4], Bl[4];
            #pragma unroll
            for (int ntl = 0; ntl < 4; ntl++) {
                int base = ((ks * 8 + nh * 4 + ntl) * 32 + l) * 2;
                Bh[ntl] = *reinterpret_cast<const uint2*>(&S.BH[cur][base]);
                Bl[ntl] = *reinterpret_cast<const uint2*>(&S.BL[cur][base]);
            }
            uint32_t AL0[4], AL1[4];
            {
                uint4 a0 = *reinterpret_cast<const uint4*>(&S.Al[mblk][0][ks][l][0]);
                uint4 a1 = *reinterpret_cast<const uint4*>(&S.Al[mblk][1][ks][l][0]);
                AL0[0] = a0.x; AL0[1] = a0.y; AL0[2] = a0.z; AL0[3] = a0.w;
                AL1[0] = a1.x; AL1[1] = a1.y; AL1[2] = a1.z; AL1[3] = a1.w;
            }
            // Pass 1: Ah x Bh  (8 distinct accumulators back-to-back)
            #pragma unroll
            for (int ntl = 0; ntl < 4; ntl++) {
                mma_bf16(C[0][ntl], Ah[0][ks], Bh[ntl].x, Bh[ntl].y);
                mma_bf16(C[1][ntl], Ah[1][ks], Bh[ntl].x, Bh[ntl].y);
            }
            // Pass 2: Ah x Bl
            #pragma unroll
            for (int ntl = 0; ntl < 4; ntl++) {
                mma_bf16(C[0][ntl], Ah[0][ks], Bl[ntl].x, Bl[ntl].y);
                mma_bf16(C[1][ntl], Ah[1][ks], Bl[ntl].x, Bl[ntl].y);
            }
            // Pass 3: Al x Bh
            #pragma unroll
            for (int ntl = 0; ntl < 4; ntl++) {
                mma_bf16(C[0][ntl], AL0, Bh[ntl].x, Bh[ntl].y);
                mma_bf16(C[1][ntl], AL1, Bh[ntl].x, Bh[ntl].y);
            }
        }

        // ---- convert next batch early (shortens tail to the barrier) ----
        if (bn < Btot) convert(cur ^ 1);

        // ---- exact rank-2 update (k = 48, 49) on the fma pipe ----
        #pragma unroll
        for (int ntl = 0; ntl < 4; ntl++) {
            int e0 = nh * 32 + ntl * 8 + 2 * la;
            float2 x48 = *reinterpret_cast<const float2*>(&S.Xt[cur][e0]);
            float2 x49 = *reinterpret_cast<const float2*>(&S.Xt[cur][64 + e0]);
            #pragma unroll
            for (int mt = 0; mt < 2; mt++) {
                C[mt][ntl][0] = fmaf(tT[mt][0][0], x48.x,
                                fmaf(tT[mt][0][1], x49.x, C[mt][ntl][0]));
                C[mt][ntl][1] = fmaf(tT[mt][0][0], x48.y,
                                fmaf(tT[mt][0][1], x49.y, C[mt][ntl][1]));
                C[mt][ntl][2] = fmaf(tT[mt][1][0], x48.x,
                                fmaf(tT[mt][1][1], x49.x, C[mt][ntl][2]));
                C[mt][ntl][3] = fmaf(tT[mt][1][0], x48.y,
                                fmaf(tT[mt][1][1], x49.y, C[mt][ntl][3]));
            }
        }

        // ---- epilogue: sum_e proj^2, reduce within quad ----
        float s[2][2] = {{0.f, 0.f}, {0.f, 0.f}};
        #pragma unroll
        for (int mt = 0; mt < 2; mt++)
            #pragma unroll
            for (int ntl = 0; ntl < 4; ntl++) {
                s[mt][0] = fmaf(C[mt][ntl][0], C[mt][ntl][0],
                           fmaf(C[mt][ntl][1], C[mt][ntl][1], s[mt][0]));
                s[mt][1] = fmaf(C[mt][ntl][2], C[mt][ntl][2],
                           fmaf(C[mt][ntl][3], C[mt][ntl][3], s[mt][1]));
            }
        #pragma unroll
        for (int mt = 0; mt < 2; mt++)
            #pragma unroll
            for (int h = 0; h < 2; h++) {
                float v = s[mt][h];
                v += __shfl_xor_sync(0xffffffffu, v, 1);
                v += __shfl_xor_sync(0xffffffffu, v, 2);
                s[mt][h] = v;
            }
        if (la == 0) {
            #pragma unroll
            for (int mt = 0; mt < 2; mt++) {
                S.red[cur][nh][mblk * 32 + mt * 16 + lg]     = s[mt][0];
                S.red[cur][nh][mblk * 32 + mt * 16 + lg + 8] = s[mt][1];
            }
        }

        __syncthreads();                       // single barrier per batch

        if (t < D_DIM)
            out[(size_t)b * D_DIM + t] = S.red[cur][0][t] + S.red[cur][1][t];
    }
}

extern "C" void kernel_launch(void* const* d_in, const int* in_sizes, int n_in,
                              void* d_out, int out_size) {
    int xi = 0, ti = 1;
    if (n_in >= 2 && in_sizes[0] < in_sizes[1]) { xi = 1; ti = 0; }

    const float* X     = (const float*)d_in[xi];
    const float* Theta = (const float*)d_in[ti];
    float*       out   = (float*)d_out;
    int Btot = in_sizes[xi] / (F_DIM * E_DIM);

    cudaFuncSetAttribute(ip_hmma5, cudaFuncAttributeMaxDynamicSharedMemorySize,
                         (int)sizeof(Smem));
    ip_hmma5<<<GRID, NTHREADS, sizeof(Smem)>>>(X, Theta, out, Btot);
}